// round 4
// baseline (speedup 1.0000x reference)
#include <cuda_runtime.h>
#include <cstdint>

// NTXentLoss: N=8192 samples, D=128 features, fp32.
// loss = mean_i( log(sum_{j!=i} exp(cos(i,j)/T)) - cos(i,pos(i))/T ),  pos(i)=(i+N/2)%N
// Streaming exp-sum (no NxN materialization). Logits bounded in [-10,10] -> no max-shift needed.

#define NN 8192
#define DD 128
#define BM 64     // rows per block
#define BN 128    // cols per tile
// 256 threads: 16 tx (cols) x 16 ty (rows); micro-tile 4 rows x 8 cols per thread.

__device__ float g_zT[DD * NN];   // normalized data, K-major: zT[k][n]

// ---------------------------------------------------------------------------
// Phase 1: row-normalize, store transposed (k-major) so GEMM tiles need no
// in-smem transpose (all smem traffic becomes conflict-free float4).
// ---------------------------------------------------------------------------
__global__ void __launch_bounds__(128) nt_normalize(const float* __restrict__ x) {
    const int row = blockIdx.x;
    const int t = threadIdx.x;            // = k
    const float v = x[row * DD + t];
    float ss = v * v;
#pragma unroll
    for (int o = 16; o; o >>= 1) ss += __shfl_xor_sync(0xffffffffu, ss, o);
    __shared__ float ws[4];
    if ((t & 31) == 0) ws[t >> 5] = ss;
    __syncthreads();
    const float tot = ws[0] + ws[1] + ws[2] + ws[3];
    const float inv = 1.0f / fmaxf(sqrtf(tot), 1e-8f);
    g_zT[t * NN + row] = v * inv;
}

__global__ void nt_zero(float* __restrict__ out) {
    if (threadIdx.x == 0) out[0] = 0.0f;
}

__device__ __forceinline__ void cp16(uint32_t saddr, const float* g) {
    asm volatile("cp.async.cg.shared.global [%0], [%1], 16;\n" :: "r"(saddr), "l"(g));
}

// ---------------------------------------------------------------------------
// Phase 2: per block: 64 rows x all 8192 cols, K=128 resident.
// A tile (64x128) loaded once; B tiles (128x128) double-buffered via cp.async.
// ---------------------------------------------------------------------------
__global__ void __launch_bounds__(256) nt_main(float* __restrict__ out) {
    extern __shared__ float sm[];
    float* As = sm;                 // [128][64]  k-major,  8192 floats (32 KB)
    float* B0 = sm + DD * BM;       // [128][128] k-major, 16384 floats (64 KB)
    float* B1 = B0 + DD * BN;       // second buffer           (64 KB)

    const int tid = threadIdx.x;
    const int tx = tid & 15;        // col group
    const int ty = tid >> 4;        // row group
    const int rowBase = blockIdx.x * BM;

    // Load A tile: As[k][r], float4 index f = k*16 + c4. Conflict-free.
#pragma unroll
    for (int i = 0; i < (DD * BM / 4) / 256; ++i) {
        int f = tid + i * 256;
        int k = f >> 4, c4 = f & 15;
        reinterpret_cast<float4*>(As)[f] =
            *reinterpret_cast<const float4*>(g_zT + (size_t)k * NN + rowBase + (c4 << 2));
    }

    // Prefetch B tile 0
#pragma unroll
    for (int i = 0; i < (DD * BN / 4) / 256; ++i) {
        int f = tid + i * 256;
        int k = f >> 5, c4 = f & 31;
        cp16((uint32_t)__cvta_generic_to_shared(B0 + (f << 2)),
             g_zT + (size_t)k * NN + (c4 << 2));
    }
    asm volatile("cp.async.commit_group;\n");

    float sumE[4] = {0.f, 0.f, 0.f, 0.f};
    float posv[4] = {0.f, 0.f, 0.f, 0.f};

    const int nT = NN / BN;   // 64 column tiles
    for (int tt = 0; tt < nT; ++tt) {
        float* cur = (tt & 1) ? B1 : B0;
        float* nxt = (tt & 1) ? B0 : B1;

        asm volatile("cp.async.wait_group 0;\n" ::: "memory");
        __syncthreads();   // cur ready for all; everyone done reading nxt (= prev cur)

        if (tt + 1 < nT) {
            const int cb = (tt + 1) * BN;
#pragma unroll
            for (int i = 0; i < (DD * BN / 4) / 256; ++i) {
                int f = tid + i * 256;
                int k = f >> 5, c4 = f & 31;
                cp16((uint32_t)__cvta_generic_to_shared(nxt + (f << 2)),
                     g_zT + (size_t)k * NN + cb + (c4 << 2));
            }
            asm volatile("cp.async.commit_group;\n");
        }

        float acc[4][8];
#pragma unroll
        for (int i = 0; i < 4; ++i)
#pragma unroll
            for (int j = 0; j < 8; ++j) acc[i][j] = 0.f;

        const float4* A4 = reinterpret_cast<const float4*>(As);
        const float4* C4 = reinterpret_cast<const float4*>(cur);
#pragma unroll 8
        for (int k = 0; k < DD; ++k) {
            float4 a  = A4[k * 16 + ty];          // broadcast across tx lanes
            float4 b0 = C4[k * 32 + tx];          // 512B spread, conflict-free
            float4 b1 = C4[k * 32 + tx + 16];
            float av[4] = {a.x, a.y, a.z, a.w};
            float bv[8] = {b0.x, b0.y, b0.z, b0.w, b1.x, b1.y, b1.z, b1.w};
#pragma unroll
            for (int i = 0; i < 4; ++i)
#pragma unroll
                for (int j = 0; j < 8; ++j)
                    acc[i][j] = fmaf(av[i], bv[j], acc[i][j]);
        }

        // Epilogue: logits = dot/T; skip diagonal; capture positive pair.
        const int colBase = tt * BN;
#pragma unroll
        for (int i = 0; i < 4; ++i) {
            const int row  = rowBase + (ty << 2) + i;
            const int pcol = (row + NN / 2) & (NN - 1);
#pragma unroll
            for (int j = 0; j < 8; ++j) {
                const int col = colBase + ((j < 4) ? ((tx << 2) + j)
                                                   : (64 + (tx << 2) + (j - 4)));
                const float v = acc[i][j] * 10.0f;      // 1/TEMPERATURE
                const float e = __expf(v);
                sumE[i] += (col == row) ? 0.0f : e;     // diag masked
                if (col == pcol) posv[i] = v;           // exactly one writer per row
            }
        }
        // no trailing sync: next iteration's wait+syncthreads covers buffer reuse
    }

    // Reduce across the 16 tx lanes sharing each row (warp = {2 ty groups} x 16 tx).
    float part = 0.0f;
#pragma unroll
    for (int i = 0; i < 4; ++i) {
        float s = sumE[i], p = posv[i];
#pragma unroll
        for (int o = 8; o; o >>= 1) {
            s += __shfl_xor_sync(0xffffffffu, s, o);
            p += __shfl_xor_sync(0xffffffffu, p, o);   // sum works: one nonzero contributor
        }
        if (tx == 0) part += logf(s) - p;
    }
    if (tx == 0) atomicAdd(out, part * (1.0f / NN));
}

// ---------------------------------------------------------------------------
extern "C" void kernel_launch(void* const* d_in, const int* in_sizes, int n_in,
                              void* d_out, int out_size) {
    (void)in_sizes; (void)n_in; (void)out_size;
    const float* x = (const float*)d_in[0];
    float* out = (float*)d_out;

    nt_normalize<<<NN, DD>>>(x);
    nt_zero<<<1, 32>>>(out);

    const int smem = (DD * BM + 2 * DD * BN) * (int)sizeof(float);  // 160 KB
    cudaFuncSetAttribute(nt_main, cudaFuncAttributeMaxDynamicSharedMemorySize, smem);
    nt_main<<<NN / BM, 256, smem>>>(out);
}

// round 6
// speedup vs baseline: 6.6045x; 6.6045x over previous
#include <cuda_runtime.h>
#include <cuda_fp16.h>
#include <cstdint>

// NTXentLoss N=8192, D=128 fp32.
// loss = mean_i( log(sum_{j!=i} exp(10*cos(i,j))) - 10*cos(i, i^4096) )
// Tensor path: single fp16 GEMM pass via mma.sync.m16n8k16 (register accumulators),
// streaming exp-sum epilogue (logits bounded in [-10,10] -> no max shift).
// Positive-pair term computed exactly in fp32 by a separate tiny kernel.

#define NN 8192
#define DD 128
#define KPADB 272              // padded smem row: 128 halves + 8 pad = 272 bytes
#define TILEB (128 * KPADB)    // one 128x128 fp16 tile in smem (34816 B)
#define EXK 14.4269504088896340736f   // 10 * log2(e)

__device__ float  g_zf[NN * DD];        // normalized fp32 (for exact pos term)
__device__ __half g_h[NN * DD];         // normalized fp16 [n][k]
__device__ float  g_sumE[NN];

__device__ __forceinline__ uint32_t smem_u32(const void* p) {
    return (uint32_t)__cvta_generic_to_shared(p);
}
__device__ __forceinline__ void cp16(uint32_t dst, const void* src) {
    asm volatile("cp.async.cg.shared.global [%0], [%1], 16;\n" :: "r"(dst), "l"(src));
}
__device__ __forceinline__ float ex2f(float x) {
    float r; asm("ex2.approx.f32 %0, %1;" : "=f"(r) : "f"(x)); return r;
}
__device__ __forceinline__ void ldsm_x4(uint32_t a, uint32_t r[4]) {
    asm volatile("ldmatrix.sync.aligned.m8n8.x4.shared.b16 {%0,%1,%2,%3}, [%4];"
                 : "=r"(r[0]), "=r"(r[1]), "=r"(r[2]), "=r"(r[3]) : "r"(a));
}
__device__ __forceinline__ void mma16816(float c[4], const uint32_t a[4],
                                         const uint32_t b[2]) {
    asm volatile(
        "mma.sync.aligned.m16n8k16.row.col.f32.f16.f16.f32 "
        "{%0,%1,%2,%3}, {%4,%5,%6,%7}, {%8,%9}, {%0,%1,%2,%3};"
        : "+f"(c[0]), "+f"(c[1]), "+f"(c[2]), "+f"(c[3])
        : "r"(a[0]), "r"(a[1]), "r"(a[2]), "r"(a[3]), "r"(b[0]), "r"(b[1]));
}

// ---------------------------------------------------------------------------
// Phase 1: row-normalize; emit fp32 (for pos) + fp16 (for GEMM).
// ---------------------------------------------------------------------------
__global__ void __launch_bounds__(512) nt_normalize(const float* __restrict__ x) {
    const int t = threadIdx.x;
    const int rl = t >> 7, k = t & 127;
    const int row = (blockIdx.x << 2) + rl;
    const float v = x[row * DD + k];
    float ss = v * v;
#pragma unroll
    for (int o = 16; o; o >>= 1) ss += __shfl_xor_sync(0xffffffffu, ss, o);
    __shared__ float ws[16];
    if ((k & 31) == 0) ws[(rl << 2) + (k >> 5)] = ss;
    __syncthreads();
    const float tot = ws[rl << 2] + ws[(rl << 2) + 1] + ws[(rl << 2) + 2] + ws[(rl << 2) + 3];
    const float z = v * (1.0f / fmaxf(sqrtf(tot), 1e-8f));
    g_zf[row * DD + k] = z;
    g_h[row * DD + k] = __float2half(z);
}

__global__ void __launch_bounds__(256) nt_zero(float* __restrict__ out) {
    const int i = blockIdx.x * 256 + threadIdx.x;
    g_sumE[i] = 0.0f;
    if (i == 0) out[0] = 0.0f;
}

// Load one [128 samples][128 k] fp16 tile into padded smem (272B rows).
__device__ __forceinline__ void load_tile(uint32_t sdst, const __half* __restrict__ g,
                                          int sbase, int tid) {
#pragma unroll
    for (int i = 0; i < 8; ++i) {          // 2048 x 16B / 256 threads
        const int f = tid + (i << 8);
        const int row = f >> 4, kb = f & 15;
        cp16(sdst + row * KPADB + (kb << 4),
             (const char*)g + ((size_t)(sbase + row) << 8) + (kb << 4));
    }
}

// ---------------------------------------------------------------------------
// Phase 2: GEMM + streaming exp-sum. Grid 128 = 64 row-blocks x 2 col-halves.
// 8 warps as 2(M) x 4(N); warp tile 64x32; K=128 resident.
// ---------------------------------------------------------------------------
__global__ void __launch_bounds__(256) nt_main() {
    extern __shared__ char sm[];
    __shared__ float s_red[128];

    const int tid = threadIdx.x, wid = tid >> 5, lane = tid & 31;
    const int wM = wid >> 2, wN = wid & 3;
    const int rowBase = (blockIdx.x >> 1) * 128;
    const int colHalf = (blockIdx.x & 1) * 4096;
    const uint32_t smem0 = smem_u32(sm);
    const uint32_t aBase = smem0;                  // A tile
    const uint32_t bBase[2] = {smem0 + TILEB, smem0 + 2 * TILEB};

    load_tile(aBase, g_h, rowBase, tid);
    load_tile(bBase[0], g_h, colHalf, tid);
    asm volatile("cp.async.commit_group;\n");

    if (tid < 128) s_red[tid] = 0.0f;

    // ldmatrix lane addresses (byte offsets within tile), constant per thread:
    // A: row = wM*64 + mf*16 + (lane&15), colbyte = ks*32 + (lane>>4)*16
    const uint32_t aLane = (uint32_t)((wM * 64 + (lane & 15)) * KPADB + ((lane >> 4) << 4));
    // B: row = wN*32 + nfp*16 + ((lane>>4)<<3) + (lane&7), colbyte = ks*32 + ((lane>>3)&1)*16
    const uint32_t bLane = (uint32_t)((wN * 32 + ((lane >> 4) << 3) + (lane & 7)) * KPADB
                                      + (((lane >> 3) & 1) << 4));

    float sE[8];
#pragma unroll
    for (int i = 0; i < 8; ++i) sE[i] = 0.0f;

    const int thRow0 = rowBase + wM * 64 + (lane >> 2);   // + mf*16 + rh*8
    const int thCol0 = wN * 32 + ((lane & 3) << 1);       // + cb + nf*8 + j

    for (int t = 0; t < 32; ++t) {
        asm volatile("cp.async.wait_group 0;\n" ::: "memory");
        __syncthreads();
        if (t + 1 < 32) {
            load_tile(bBase[(t + 1) & 1], g_h, colHalf + (t + 1) * 128, tid);
            asm volatile("cp.async.commit_group;\n");
        }
        const uint32_t bb = bBase[t & 1];

        float c[4][4][4];
#pragma unroll
        for (int mf = 0; mf < 4; ++mf)
#pragma unroll
            for (int nf = 0; nf < 4; ++nf)
#pragma unroll
                for (int r = 0; r < 4; ++r) c[mf][nf][r] = 0.0f;

#pragma unroll
        for (int ks = 0; ks < 8; ++ks) {
            uint32_t a[4][4], b[4][2];
#pragma unroll
            for (int mf = 0; mf < 4; ++mf)
                ldsm_x4(aBase + aLane + (uint32_t)(mf * 16 * KPADB) + (ks << 5), a[mf]);
#pragma unroll
            for (int np = 0; np < 2; ++np) {
                uint32_t r4[4];
                ldsm_x4(bb + bLane + (uint32_t)(np * 16 * KPADB) + (ks << 5), r4);
                b[2 * np][0] = r4[0]; b[2 * np][1] = r4[1];
                b[2 * np + 1][0] = r4[2]; b[2 * np + 1][1] = r4[3];
            }
#pragma unroll
            for (int mf = 0; mf < 4; ++mf)
#pragma unroll
                for (int nf = 0; nf < 4; ++nf)
                    mma16816(c[mf][nf], a[mf], b[nf]);
        }

        // Epilogue on register accumulators.
        const int cb = colHalf + t * 128;
        if (cb == rowBase) {            // diag tile: mask col==row
#pragma unroll
            for (int mf = 0; mf < 4; ++mf)
#pragma unroll
                for (int nf = 0; nf < 4; ++nf)
#pragma unroll
                    for (int r = 0; r < 4; ++r) {
                        const int row = thRow0 + mf * 16 + ((r >> 1) << 3);
                        const int col = cb + thCol0 + nf * 8 + (r & 1);
                        const float e = ex2f(c[mf][nf][r] * EXK);
                        sE[mf * 2 + (r >> 1)] += (col == row) ? 0.0f : e;
                    }
        } else {                         // fast path
#pragma unroll
            for (int mf = 0; mf < 4; ++mf)
#pragma unroll
                for (int nf = 0; nf < 4; ++nf)
#pragma unroll
                    for (int r = 0; r < 4; ++r)
                        sE[mf * 2 + (r >> 1)] += ex2f(c[mf][nf][r] * EXK);
        }
    }

    // Reduce: lanes 4q..4q+3 share rows -> shfl; then smem atomics; then global.
#pragma unroll
    for (int i = 0; i < 8; ++i) {
        sE[i] += __shfl_xor_sync(0xffffffffu, sE[i], 1);
        sE[i] += __shfl_xor_sync(0xffffffffu, sE[i], 2);
    }
    __syncthreads();            // s_red zero-init visible
    if ((lane & 3) == 0) {
        const int lr0 = wM * 64 + (lane >> 2);
#pragma unroll
        for (int i = 0; i < 8; ++i)
            atomicAdd(&s_red[lr0 + (i >> 1) * 16 + (i & 1) * 8], sE[i]);
    }
    __syncthreads();
    if (tid < 128) atomicAdd(&g_sumE[rowBase + tid], s_red[tid]);
}

// ---------------------------------------------------------------------------
// Phase 3: pos_i = 10*dot(z_i, z_{i^4096}) in fp32; loss mean.
// ---------------------------------------------------------------------------
__global__ void __launch_bounds__(256) nt_final(float* __restrict__ out) {
    const int w = threadIdx.x >> 5, lane = threadIdx.x & 31;
    const int row = (blockIdx.x << 3) + w;
    const int mate = row ^ (NN / 2);
    const float4 a = reinterpret_cast<const float4*>(g_zf)[row * 32 + lane];
    const float4 b = reinterpret_cast<const float4*>(g_zf)[mate * 32 + lane];
    float d = a.x * b.x + a.y * b.y + a.z * b.z + a.w * b.w;
#pragma unroll
    for (int o = 16; o; o >>= 1) d += __shfl_xor_sync(0xffffffffu, d, o);
    __shared__ float ws[8];
    if (lane == 0) ws[w] = logf(g_sumE[row]) - 10.0f * d;
    __syncthreads();
    if (threadIdx.x == 0) {
        float s = 0.0f;
#pragma unroll
        for (int i = 0; i < 8; ++i) s += ws[i];
        atomicAdd(out, s * (1.0f / NN));
    }
}

// ---------------------------------------------------------------------------
extern "C" void kernel_launch(void* const* d_in, const int* in_sizes, int n_in,
                              void* d_out, int out_size) {
    (void)in_sizes; (void)n_in; (void)out_size;
    const float* x = (const float*)d_in[0];
    float* out = (float*)d_out;

    nt_normalize<<<NN / 4, 512>>>(x);
    nt_zero<<<NN / 256, 256>>>(out);

    const int smem = 3 * TILEB;   // 104448 B
    cudaFuncSetAttribute(nt_main, cudaFuncAttributeMaxDynamicSharedMemorySize, smem);
    nt_main<<<128, 256, smem>>>();

    nt_final<<<NN / 8, 256>>>(out);
}